// round 5
// baseline (speedup 1.0000x reference)
#include <cuda_runtime.h>

#define OUT_DIM 128
#define RKHS_DIM 20
#define ROWS_PER_ITER 4
#define BLOCKS_PER_SM 6

__global__ __launch_bounds__(OUT_DIM, BLOCKS_PER_SM)
void kde_time_encoder_kernel(
    const float* __restrict__ t_diff,
    const void*  __restrict__ kde_idx_raw,
    const void*  __restrict__ kde_mask_raw,
    const float* __restrict__ kde_table,
    const float* __restrict__ W_proj,
    const float* __restrict__ b_proj,
    const float* __restrict__ W_fb,
    const float* __restrict__ b_fb,
    float* __restrict__ out,
    int B)
{
    const int o = threadIdx.x;

    // Per-thread weight row for this output column: loaded once per persistent block.
    float wp[RKHS_DIM];
#pragma unroll
    for (int k = 0; k < RKHS_DIM; ++k) wp[k] = W_proj[o * RKHS_DIM + k];
    const float bp  = b_proj[o];
    const float wfb = W_fb[o];     // W_fb is [OUT, 1]
    const float bfb = b_fb[o];

    // ---- Deterministic input-layout detection (pure function of input data) ----
    // kde_mask: jax bool may arrive as 1-byte bool or as int32 0/1.
    //   int32 little-endian 0/1 values -> bytes 1..3 of every element are 0.
    //   byte-bool random 0/1 -> some of those byte positions are 1 (P(miss) ~ 2^-192).
    // kde_idx: may be int32 or int64. int64 values < 2^31 -> every odd 32-bit word is 0.
    //   int32 random indices in [0, 500000) -> P(32 consecutive odd words all 0) ~ 0.
    __shared__ int s_mask_is_u8;
    __shared__ int s_idx_is_64;
    if (o == 0) {
        const uchar4* mb = (const uchar4*)kde_mask_raw;
        unsigned f = 0;
#pragma unroll
        for (int i = 0; i < 64; ++i) { uchar4 u = mb[i]; f |= (unsigned)u.y | u.z | u.w; }
        s_mask_is_u8 = (f != 0);

        const int* iw = (const int*)kde_idx_raw;
        int nz = 0;
#pragma unroll
        for (int i = 0; i < 32; ++i) nz |= iw[2 * i + 1];
        s_idx_is_64 = (nz == 0);
    }
    __syncthreads();
    const bool mask_is_u8 = (s_mask_is_u8 != 0);
    const bool idx_is_64  = (s_idx_is_64 != 0);
    const unsigned char* mask_u8  = (const unsigned char*)kde_mask_raw;
    const int*           mask_i32 = (const int*)kde_mask_raw;
    const int*           idx_i32  = (const int*)kde_idx_raw;
    const long long*     idx_i64  = (const long long*)kde_idx_raw;

    const int stride = gridDim.x * ROWS_PER_ITER;
    for (int r0 = blockIdx.x * ROWS_PER_ITER; r0 < B; r0 += stride) {
#pragma unroll
        for (int j = 0; j < ROWS_PER_ITER; ++j) {
            const int r = r0 + j;
            if (r >= B) break;

            // mask is identical across the block for a given row -> uniform branch.
            const int m = mask_is_u8 ? (int)mask_u8[r] : mask_i32[r];
            float val;
            if (m) {
                const long long idx = idx_is_64 ? idx_i64[r] : (long long)idx_i32[r];
                // 20 floats = 80 bytes, 16B-aligned (idx*80). Uniform address across
                // the warp -> 5 single-request LDG.128 broadcasts.
                const float4* kv = (const float4*)(kde_table + (size_t)idx * RKHS_DIM);
                float4 a  = __ldg(kv + 0);
                float4 b4 = __ldg(kv + 1);
                float4 c  = __ldg(kv + 2);
                float4 d  = __ldg(kv + 3);
                float4 e  = __ldg(kv + 4);
                // 4 independent accumulator chains: dependent-chain depth 5 FMAs (~20 cyc).
                float s0 = fmaf(a.x, wp[0], bp);
                float s1 = a.y * wp[1];
                float s2 = a.z * wp[2];
                float s3 = a.w * wp[3];
                s0 = fmaf(b4.x, wp[4],  s0); s1 = fmaf(b4.y, wp[5],  s1);
                s2 = fmaf(b4.z, wp[6],  s2); s3 = fmaf(b4.w, wp[7],  s3);
                s0 = fmaf(c.x,  wp[8],  s0); s1 = fmaf(c.y,  wp[9],  s1);
                s2 = fmaf(c.z,  wp[10], s2); s3 = fmaf(c.w,  wp[11], s3);
                s0 = fmaf(d.x,  wp[12], s0); s1 = fmaf(d.y,  wp[13], s1);
                s2 = fmaf(d.z,  wp[14], s2); s3 = fmaf(d.w,  wp[15], s3);
                s0 = fmaf(e.x,  wp[16], s0); s1 = fmaf(e.y,  wp[17], s1);
                s2 = fmaf(e.z,  wp[18], s2); s3 = fmaf(e.w,  wp[19], s3);
                val = (s0 + s1) + (s2 + s3);
            } else {
                val = cosf(fmaf(t_diff[r], wfb, bfb));
            }
            // Coalesced 512B row write.
            out[(size_t)r * OUT_DIM + o] = val;
        }
    }
}

extern "C" void kernel_launch(void* const* d_in, const int* in_sizes, int n_in,
                              void* d_out, int out_size)
{
    // metadata order: 0 src, 1 dst, 2 t_diff, 3 kde_idx, 4 kde_mask,
    //                 5 kde_table, 6 W_proj, 7 b_proj, 8 W_fb, 9 b_fb
    const float* t_diff    = (const float*)d_in[2];
    const void*  kde_idx   = d_in[3];
    const void*  kde_mask  = d_in[4];
    const float* kde_table = (const float*)d_in[5];
    const float* W_proj    = (const float*)d_in[6];
    const float* b_proj    = (const float*)d_in[7];
    const float* W_fb      = (const float*)d_in[8];
    const float* b_fb      = (const float*)d_in[9];
    float* out = (float*)d_out;
    const int B = in_sizes[2];

    const int grid = 148 * BLOCKS_PER_SM;  // persistent-style grid-stride
    kde_time_encoder_kernel<<<grid, OUT_DIM>>>(
        t_diff, kde_idx, kde_mask, kde_table,
        W_proj, b_proj, W_fb, b_fb, out, B);
}

// round 10
// speedup vs baseline: 2.9873x; 2.9873x over previous
#include <cuda_runtime.h>

#define OUT_DIM 128
#define RKHS_DIM 20
#define TILE 128
#define BLOCKS_PER_SM 3

typedef unsigned long long ull;

__device__ __forceinline__ ull ffma2(ull a, ull b, ull c) {
    ull d;
    asm("fma.rn.f32x2 %0, %1, %2, %3;" : "=l"(d) : "l"(a), "l"(b), "l"(c));
    return d;
}
__device__ __forceinline__ ull fmul2(ull a, ull b) {
    ull d;
    asm("mul.rn.f32x2 %0, %1, %2;" : "=l"(d) : "l"(a), "l"(b));
    return d;
}
__device__ __forceinline__ float pair_sum(ull v) {
    unsigned lo, hi;
    asm("mov.b64 {%0, %1}, %2;" : "=r"(lo), "=r"(hi) : "l"(v));
    return __uint_as_float(lo) + __uint_as_float(hi);
}
// Cody-Waite range reduction (exact for |n|<2^10) + HW cos on reduced arg.
// args here are at most ~3000 -> n <= ~500, so n*C1 (9-bit C1) is exact.
__device__ __forceinline__ float fast_cos(float x) {
    float n = rintf(x * 0.15915494f);          // 1/(2*pi)
    float r = fmaf(n, -6.28125f, x);           // C1: exact product
    r = fmaf(n, -1.9353071795864e-3f, r);      // C2 = 2*pi - C1
    return __cosf(r);
}

__global__ __launch_bounds__(OUT_DIM, BLOCKS_PER_SM)
void kde_time_encoder_kernel(
    const float* __restrict__ t_diff,
    const void*  __restrict__ kde_idx_raw,
    const void*  __restrict__ kde_mask_raw,
    const float* __restrict__ kde_table,
    const float* __restrict__ W_proj,
    const float* __restrict__ b_proj,
    const float* __restrict__ W_fb,
    const float* __restrict__ b_fb,
    float* __restrict__ out,
    int B)
{
    const int tid  = threadIdx.x;
    const int warp = tid >> 5;
    const int lane = tid & 31;
    const int c0   = lane * 4;           // this lane owns output cols c0..c0+3

    // ---- Per-thread weights for 4 columns, packed as f32x2 pairs (80 regs) ----
    // W_proj row = 20 floats = 80 bytes -> 8B-aligned, read as 10 ull.
    ull w2[4][10];
    float bp[4], wfb[4], bfb[4];
#pragma unroll
    for (int cc = 0; cc < 4; ++cc) {
        const ull* wr = (const ull*)(W_proj + (size_t)(c0 + cc) * RKHS_DIM);
#pragma unroll
        for (int p = 0; p < 10; ++p) w2[cc][p] = wr[p];
        bp[cc]  = b_proj[c0 + cc];
        wfb[cc] = W_fb[c0 + cc];
        bfb[cc] = b_fb[c0 + cc];
    }

    // ---- Deterministic input-layout detection (same logic that passed R5) ----
    __shared__ int s_mask_is_u8, s_idx_is_64;
    if (tid == 0) {
        const uchar4* mb = (const uchar4*)kde_mask_raw;
        unsigned f = 0;
#pragma unroll
        for (int i = 0; i < 64; ++i) { uchar4 u = mb[i]; f |= (unsigned)u.y | u.z | u.w; }
        s_mask_is_u8 = (f != 0);
        const int* iw = (const int*)kde_idx_raw;
        int nz = 0;
#pragma unroll
        for (int i = 0; i < 32; ++i) nz |= iw[2 * i + 1];
        s_idx_is_64 = (nz == 0);
    }
    __syncthreads();
    const bool mask_is_u8 = (s_mask_is_u8 != 0);
    const bool idx_is_64  = (s_idx_is_64 != 0);
    const unsigned char* mask_u8  = (const unsigned char*)kde_mask_raw;
    const int*           mask_i32 = (const int*)kde_mask_raw;
    const int*           idx_i32  = (const int*)kde_idx_raw;
    const long long*     idx_i64  = (const long long*)kde_idx_raw;

    // ---- Tile staging buffers ----
    __shared__ float4 s_vec[TILE][5];   // gathered kde vectors (80B/row)
    __shared__ int    s_idx[TILE];      // masked ? idx : -1
    __shared__ float  s_t[TILE];

    const float4* table4 = (const float4*)kde_table;
    const int tiles = (B + TILE - 1) / TILE;

    for (int tile = blockIdx.x; tile < tiles; tile += gridDim.x) {
        const int base = tile * TILE;
        __syncthreads();   // protect smem reuse from previous tile's compute

        // Stage A: per-row scalars (coalesced, one row per thread)
        {
            const int r = base + tid;
            if (r < B) {
                const int m = mask_is_u8 ? (int)mask_u8[r] : mask_i32[r];
                long long idx = idx_is_64 ? idx_i64[r] : (long long)idx_i32[r];
                s_idx[tid] = m ? (int)idx : -1;
                s_t[tid]   = t_diff[r];
            } else {
                s_idx[tid] = -1;
                s_t[tid]   = 0.0f;
            }
        }
        __syncthreads();

        // Stage B: cooperative gather of masked rows' vectors.
        // 128 rows x 8 slots (5 real) = 1024 tasks, 8 independent LDG.128/thread.
#pragma unroll
        for (int k = 0; k < 8; ++k) {
            const int task = tid + OUT_DIM * k;
            const int j = task >> 3;
            const int q = task & 7;
            const int idx = s_idx[j];
            if (q < 5 && idx >= 0)
                s_vec[j][q] = __ldg(table4 + (size_t)idx * 5 + q);
        }
        __syncthreads();

        // Stage C: warp w computes rows [w*32, w*32+32), 4 cols per lane.
        for (int i = 0; i < 32; ++i) {
            const int j = warp * 32 + i;
            const int r = base + j;
            if (r >= B) break;

            const int idx = s_idx[j];           // uniform per warp -> no divergence
            float v0, v1, v2, v3;
            if (idx >= 0) {
                const ull* xp = (const ull*)&s_vec[j][0];
                ull x[10];
#pragma unroll
                for (int p = 0; p < 10; ++p) x[p] = xp[p];   // LDS.64 broadcasts
                ull a0 = fmul2(x[0], w2[0][0]);
                ull a1 = fmul2(x[0], w2[1][0]);
                ull a2 = fmul2(x[0], w2[2][0]);
                ull a3 = fmul2(x[0], w2[3][0]);
#pragma unroll
                for (int p = 1; p < 10; ++p) {
                    a0 = ffma2(x[p], w2[0][p], a0);
                    a1 = ffma2(x[p], w2[1][p], a1);
                    a2 = ffma2(x[p], w2[2][p], a2);
                    a3 = ffma2(x[p], w2[3][p], a3);
                }
                v0 = pair_sum(a0) + bp[0];
                v1 = pair_sum(a1) + bp[1];
                v2 = pair_sum(a2) + bp[2];
                v3 = pair_sum(a3) + bp[3];
            } else {
                const float t = s_t[j];
                v0 = fast_cos(fmaf(t, wfb[0], bfb[0]));
                v1 = fast_cos(fmaf(t, wfb[1], bfb[1]));
                v2 = fast_cos(fmaf(t, wfb[2], bfb[2]));
                v3 = fast_cos(fmaf(t, wfb[3], bfb[3]));
            }
            // One STG.128 per lane -> fully coalesced 512B row store.
            ((float4*)(out + (size_t)r * OUT_DIM))[lane] = make_float4(v0, v1, v2, v3);
        }
    }
}

extern "C" void kernel_launch(void* const* d_in, const int* in_sizes, int n_in,
                              void* d_out, int out_size)
{
    // metadata order: 0 src, 1 dst, 2 t_diff, 3 kde_idx, 4 kde_mask,
    //                 5 kde_table, 6 W_proj, 7 b_proj, 8 W_fb, 9 b_fb
    const float* t_diff    = (const float*)d_in[2];
    const void*  kde_idx   = d_in[3];
    const void*  kde_mask  = d_in[4];
    const float* kde_table = (const float*)d_in[5];
    const float* W_proj    = (const float*)d_in[6];
    const float* b_proj    = (const float*)d_in[7];
    const float* W_fb      = (const float*)d_in[8];
    const float* b_fb      = (const float*)d_in[9];
    float* out = (float*)d_out;
    const int B = in_sizes[2];

    const int grid = 148 * BLOCKS_PER_SM;
    kde_time_encoder_kernel<<<grid, OUT_DIM>>>(
        t_diff, kde_idx, kde_mask, kde_table,
        W_proj, b_proj, W_fb, b_fb, out, B);
}

// round 12
// speedup vs baseline: 4.0267x; 1.3479x over previous
#include <cuda_runtime.h>

#define OUT_DIM 128
#define RKHS_DIM 20
#define TILE 128
#define BLOCKS_PER_SM 4

typedef unsigned long long ull;

__device__ __forceinline__ ull ffma2(ull a, ull b, ull c) {
    ull d;
    asm("fma.rn.f32x2 %0, %1, %2, %3;" : "=l"(d) : "l"(a), "l"(b), "l"(c));
    return d;
}
__device__ __forceinline__ ull pack2(float lo, float hi) {
    ull d;
    asm("mov.b64 %0, {%1, %2};" : "=l"(d) : "f"(lo), "f"(hi));
    return d;
}
__device__ __forceinline__ float pair_sum(ull v) {
    float lo, hi;
    asm("mov.b64 {%0, %1}, %2;" : "=f"(lo), "=f"(hi) : "l"(v));
    return lo + hi;
}
// Cody-Waite range reduction (exact for |n|<2^10) + HW cos on reduced arg.
__device__ __forceinline__ float fast_cos(float x) {
    float n = rintf(x * 0.15915494f);          // 1/(2*pi)
    float r = fmaf(n, -6.28125f, x);           // C1: exact 9-bit product
    r = fmaf(n, -1.9353071795864e-3f, r);      // C2 = 2*pi - C1
    return __cosf(r);
}
__device__ __forceinline__ void cp_async16(void* smem_dst, const void* gmem_src) {
    unsigned s = (unsigned)__cvta_generic_to_shared(smem_dst);
    asm volatile("cp.async.cg.shared.global [%0], [%1], 16;" :: "r"(s), "l"(gmem_src) : "memory");
}

__global__ __launch_bounds__(OUT_DIM, BLOCKS_PER_SM)
void kde_time_encoder_kernel(
    const float* __restrict__ t_diff,
    const void*  __restrict__ kde_idx_raw,
    const void*  __restrict__ kde_mask_raw,
    const float* __restrict__ kde_table,
    const float* __restrict__ W_proj,
    const float* __restrict__ b_proj,
    const float* __restrict__ W_fb,
    const float* __restrict__ b_fb,
    float* __restrict__ out,
    int B)
{
    const int tid  = threadIdx.x;
    const int warp = tid >> 5;
    const int lane = tid & 31;
    const int c0   = lane * 4;           // this lane owns output cols c0..c0+3

    // ---- Persistent per-thread state: 4 columns of weights as f32x2 pairs ----
    ull w2[4][10];
    ull bias2[4];                        // (b_proj[c], 0) — seeds the FMA chain
    float wfb[4], bfb[4];
#pragma unroll
    for (int cc = 0; cc < 4; ++cc) {
        const ull* wr = (const ull*)(W_proj + (size_t)(c0 + cc) * RKHS_DIM);
#pragma unroll
        for (int p = 0; p < 10; ++p) w2[cc][p] = wr[p];
        bias2[cc] = pack2(b_proj[c0 + cc], 0.0f);
        wfb[cc]   = W_fb[c0 + cc];
        bfb[cc]   = b_fb[c0 + cc];
    }

    // ---- Deterministic input-layout detection (pure function of input data) ----
    __shared__ int s_mask_is_u8, s_idx_is_64;
    if (tid == 0) {
        const uchar4* mb = (const uchar4*)kde_mask_raw;
        unsigned f = 0;
#pragma unroll
        for (int i = 0; i < 64; ++i) { uchar4 u = mb[i]; f |= (unsigned)u.y | u.z | u.w; }
        s_mask_is_u8 = (f != 0);
        const int* iw = (const int*)kde_idx_raw;
        int nz = 0;
#pragma unroll
        for (int i = 0; i < 32; ++i) nz |= iw[2 * i + 1];
        s_idx_is_64 = (nz == 0);
    }
    __syncthreads();
    const bool mask_is_u8 = (s_mask_is_u8 != 0);
    const bool idx_is_64  = (s_idx_is_64 != 0);
    const unsigned char* mask_u8  = (const unsigned char*)kde_mask_raw;
    const int*           mask_i32 = (const int*)kde_mask_raw;
    const int*           idx_i32  = (const int*)kde_idx_raw;
    const long long*     idx_i64  = (const long long*)kde_idx_raw;

    // ---- Tile staging ----
    __shared__ float4 s_vec[TILE][5];   // gathered kde vectors (80B/row)
    __shared__ int    s_idx[TILE];      // masked ? idx : -1
    __shared__ float  s_t[TILE];

    const float4* table4 = (const float4*)kde_table;
    const int tiles = (B + TILE - 1) / TILE;

    for (int tile = blockIdx.x; tile < tiles; tile += gridDim.x) {
        const int base = tile * TILE;
        __syncthreads();   // previous tile's compute done before smem overwrite

        // Stage A: per-row scalars (coalesced, one row per thread)
        {
            const int r = base + tid;
            if (r < B) {
                const int m = mask_is_u8 ? (int)mask_u8[r] : mask_i32[r];
                long long idx = idx_is_64 ? idx_i64[r] : (long long)idx_i32[r];
                s_idx[tid] = m ? (int)idx : -1;
                s_t[tid]   = t_diff[r];
            } else {
                s_idx[tid] = -1;
                s_t[tid]   = 0.0f;
            }
        }
        __syncthreads();

        // Stage B: cooperative gather via cp.async (no register round-trip).
        // 128 rows x 5 slots = 640 16B tasks, 5 per thread.
#pragma unroll
        for (int k = 0; k < 5; ++k) {
            const int task = tid + OUT_DIM * k;
            const int j = task / 5;
            const int q = task - j * 5;
            const int idx = s_idx[j];
            if (idx >= 0)
                cp_async16(&s_vec[j][q], table4 + (size_t)idx * 5 + q);
        }
        asm volatile("cp.async.commit_group;" ::: "memory");
        asm volatile("cp.async.wait_group 0;" ::: "memory");
        __syncthreads();

        // Stage C: warp w computes rows [w*32, w*32+32), 4 cols per lane.
        for (int i = 0; i < 32; ++i) {
            const int j = warp * 32 + i;
            const int r = base + j;
            if (r >= B) break;

            const int idx = s_idx[j];           // uniform per warp -> no divergence
            float v0, v1, v2, v3;
            if (idx >= 0) {
                ull a0 = bias2[0], a1 = bias2[1], a2 = bias2[2], a3 = bias2[3];
#pragma unroll
                for (int q = 0; q < 5; ++q) {
                    const float4 v = s_vec[j][q];       // LDS.128 broadcast
                    const ull pa = pack2(v.x, v.y);     // reg-pair rename, ~free
                    const ull pb = pack2(v.z, v.w);
                    a0 = ffma2(pa, w2[0][2*q],   a0);
                    a1 = ffma2(pa, w2[1][2*q],   a1);
                    a2 = ffma2(pa, w2[2][2*q],   a2);
                    a3 = ffma2(pa, w2[3][2*q],   a3);
                    a0 = ffma2(pb, w2[0][2*q+1], a0);
                    a1 = ffma2(pb, w2[1][2*q+1], a1);
                    a2 = ffma2(pb, w2[2][2*q+1], a2);
                    a3 = ffma2(pb, w2[3][2*q+1], a3);
                }
                v0 = pair_sum(a0);
                v1 = pair_sum(a1);
                v2 = pair_sum(a2);
                v3 = pair_sum(a3);
            } else {
                const float t = s_t[j];
                v0 = fast_cos(fmaf(t, wfb[0], bfb[0]));
                v1 = fast_cos(fmaf(t, wfb[1], bfb[1]));
                v2 = fast_cos(fmaf(t, wfb[2], bfb[2]));
                v3 = fast_cos(fmaf(t, wfb[3], bfb[3]));
            }
            // One STG.128 per lane -> fully coalesced 512B row store.
            ((float4*)(out + (size_t)r * OUT_DIM))[lane] = make_float4(v0, v1, v2, v3);
        }
    }
}

extern "C" void kernel_launch(void* const* d_in, const int* in_sizes, int n_in,
                              void* d_out, int out_size)
{
    // metadata order: 0 src, 1 dst, 2 t_diff, 3 kde_idx, 4 kde_mask,
    //                 5 kde_table, 6 W_proj, 7 b_proj, 8 W_fb, 9 b_fb
    const float* t_diff    = (const float*)d_in[2];
    const void*  kde_idx   = d_in[3];
    const void*  kde_mask  = d_in[4];
    const float* kde_table = (const float*)d_in[5];
    const float* W_proj    = (const float*)d_in[6];
    const float* b_proj    = (const float*)d_in[7];
    const float* W_fb      = (const float*)d_in[8];
    const float* b_fb      = (const float*)d_in[9];
    float* out = (float*)d_out;
    const int B = in_sizes[2];

    const int grid = 148 * BLOCKS_PER_SM;
    kde_time_encoder_kernel<<<grid, OUT_DIM>>>(
        t_diff, kde_idx, kde_mask, kde_table,
        W_proj, b_proj, W_fb, b_fb, out, B);
}

// round 15
// speedup vs baseline: 4.9502x; 1.2293x over previous
#include <cuda_runtime.h>

#define OUT_DIM 128
#define RKHS_DIM 20
#define WPB 4            // warps per block
#define BLOCKS_PER_SM 4
#define CHUNK 32         // rows per warp-chunk

typedef unsigned long long ull;

__device__ __forceinline__ ull ffma2(ull a, ull b, ull c) {
    ull d;
    asm("fma.rn.f32x2 %0, %1, %2, %3;" : "=l"(d) : "l"(a), "l"(b), "l"(c));
    return d;
}
__device__ __forceinline__ ull fmul2(ull a, ull b) {
    ull d;
    asm("mul.rn.f32x2 %0, %1, %2;" : "=l"(d) : "l"(a), "l"(b));
    return d;
}
__device__ __forceinline__ ull pack2(float lo, float hi) {
    ull d;
    asm("mov.b64 %0, {%1, %2};" : "=l"(d) : "f"(lo), "f"(hi));
    return d;
}
__device__ __forceinline__ float pair_sum_bias(ull v, float b) {
    float lo, hi;
    asm("mov.b64 {%0, %1}, %2;" : "=f"(lo), "=f"(hi) : "l"(v));
    return (lo + hi) + b;
}
// Cody-Waite range reduction (exact for |n|<2^10) + HW cos on reduced arg.
__device__ __forceinline__ float fast_cos(float x) {
    float n = rintf(x * 0.15915494f);          // 1/(2*pi)
    float r = fmaf(n, -6.28125f, x);           // C1: exact 9-bit product
    r = fmaf(n, -1.9353071795864e-3f, r);      // C2 = 2*pi - C1
    return __cosf(r);
}
__device__ __forceinline__ void cp_async16(void* smem_dst, const void* gmem_src) {
    unsigned s = (unsigned)__cvta_generic_to_shared(smem_dst);
    asm volatile("cp.async.cg.shared.global [%0], [%1], 16;" :: "r"(s), "l"(gmem_src) : "memory");
}

__global__ __launch_bounds__(OUT_DIM, BLOCKS_PER_SM)
void kde_time_encoder_kernel(
    const float* __restrict__ t_diff,
    const void*  __restrict__ kde_idx_raw,
    const void*  __restrict__ kde_mask_raw,
    const float* __restrict__ kde_table,
    const float* __restrict__ W_proj,
    const float* __restrict__ b_proj,
    const float* __restrict__ W_fb,
    const float* __restrict__ b_fb,
    float* __restrict__ out,
    int B)
{
    const int tid  = threadIdx.x;
    const int warp = tid >> 5;
    const int lane = tid & 31;
    const int c0   = lane * 4;           // this lane owns output cols c0..c0+3

    // ---- Persistent per-thread state: 4 columns of weights as f32x2 pairs ----
    ull w2[4][10];
    float bp[4], wfb[4], bfb[4];
#pragma unroll
    for (int cc = 0; cc < 4; ++cc) {
        const ull* wr = (const ull*)(W_proj + (size_t)(c0 + cc) * RKHS_DIM);
#pragma unroll
        for (int p = 0; p < 10; ++p) w2[cc][p] = wr[p];
        bp[cc]  = b_proj[c0 + cc];
        wfb[cc] = W_fb[c0 + cc];
        bfb[cc] = b_fb[c0 + cc];
    }

    // ---- Deterministic input-layout detection (pure function of input data) ----
    __shared__ int s_mask_is_u8, s_idx_is_64;
    if (tid == 0) {
        const uchar4* mb = (const uchar4*)kde_mask_raw;
        unsigned f = 0;
#pragma unroll
        for (int i = 0; i < 64; ++i) { uchar4 u = mb[i]; f |= (unsigned)u.y | u.z | u.w; }
        s_mask_is_u8 = (f != 0);
        const int* iw = (const int*)kde_idx_raw;
        int nz = 0;
#pragma unroll
        for (int i = 0; i < 32; ++i) nz |= iw[2 * i + 1];
        s_idx_is_64 = (nz == 0);
    }
    __syncthreads();                     // only block-wide barrier in the kernel
    const bool mask_is_u8 = (s_mask_is_u8 != 0);
    const bool idx_is_64  = (s_idx_is_64 != 0);
    const unsigned char* mask_u8  = (const unsigned char*)kde_mask_raw;
    const int*           mask_i32 = (const int*)kde_mask_raw;
    const int*           idx_i32  = (const int*)kde_idx_raw;
    const long long*     idx_i64  = (const long long*)kde_idx_raw;

    // ---- Warp-local double-buffered staging ----
    __shared__ float4 s_vec[WPB][2][CHUNK][5];   // gathered kde vectors
    __shared__ ull    s_meta[WPB][2][CHUNK];     // packed {idx:int, t:f32}

    const float4* table4 = (const float4*)kde_table;
    const int nchunks = (B + CHUNK - 1) / CHUNK;
    const int gstride = gridDim.x * WPB;
    int c = blockIdx.x * WPB + warp;

    // Prefetch one chunk into buffer `buf`: each lane stages its own row.
    auto prefetch = [&](int chunk, int buf) {
        const int r = chunk * CHUNK + lane;
        int   idxv = -1;
        float t    = 0.0f;
        if (r < B) {
            const int m = mask_is_u8 ? (int)mask_u8[r] : mask_i32[r];
            const long long ix = idx_is_64 ? idx_i64[r] : (long long)idx_i32[r];
            t = __ldg(t_diff + r);
            if (m) idxv = (int)ix;
        }
        s_meta[warp][buf][lane] = ((ull)(unsigned)idxv) | ((ull)__float_as_uint(t) << 32);
        if (idxv >= 0) {
            const float4* src = table4 + (size_t)idxv * 5;
#pragma unroll
            for (int q = 0; q < 5; ++q)           // 5 independent 16B cp.asyncs (MLP)
                cp_async16(&s_vec[warp][buf][lane][q], src + q);
        }
    };

    if (c < nchunks) prefetch(c, 0);
    asm volatile("cp.async.commit_group;" ::: "memory");

    int buf = 0;
    while (c < nchunks) {
        const int cn = c + gstride;
        if (cn < nchunks) prefetch(cn, buf ^ 1);   // overlaps with compute below
        asm volatile("cp.async.commit_group;" ::: "memory");
        asm volatile("cp.async.wait_group 1;" ::: "memory");  // current buf ready
        __syncwarp();                               // cross-lane smem visibility

        const int base = c * CHUNK;
#pragma unroll 4
        for (int i = 0; i < CHUNK; ++i) {
            const ull  meta = s_meta[warp][buf][i];          // LDS.64 broadcast
            const int  idx  = (int)(unsigned)(meta & 0xffffffffu);
            const int  r    = base + i;
            float v0, v1, v2, v3;
            if (idx >= 0) {                                   // warp-uniform branch
                const float4 x0 = s_vec[warp][buf][i][0];     // LDS.128 broadcasts
                const float4 x1 = s_vec[warp][buf][i][1];
                const float4 x2 = s_vec[warp][buf][i][2];
                const float4 x3 = s_vec[warp][buf][i][3];
                const float4 x4 = s_vec[warp][buf][i][4];
                const ull p0 = pack2(x0.x, x0.y), p1 = pack2(x0.z, x0.w);
                const ull p2 = pack2(x1.x, x1.y), p3 = pack2(x1.z, x1.w);
                const ull p4 = pack2(x2.x, x2.y), p5 = pack2(x2.z, x2.w);
                const ull p6 = pack2(x3.x, x3.y), p7 = pack2(x3.z, x3.w);
                const ull p8 = pack2(x4.x, x4.y), p9 = pack2(x4.z, x4.w);
                ull a0 = fmul2(p0, w2[0][0]);
                ull a1 = fmul2(p0, w2[1][0]);
                ull a2 = fmul2(p0, w2[2][0]);
                ull a3 = fmul2(p0, w2[3][0]);
                a0 = ffma2(p1, w2[0][1], a0); a1 = ffma2(p1, w2[1][1], a1);
                a2 = ffma2(p1, w2[2][1], a2); a3 = ffma2(p1, w2[3][1], a3);
                a0 = ffma2(p2, w2[0][2], a0); a1 = ffma2(p2, w2[1][2], a1);
                a2 = ffma2(p2, w2[2][2], a2); a3 = ffma2(p2, w2[3][2], a3);
                a0 = ffma2(p3, w2[0][3], a0); a1 = ffma2(p3, w2[1][3], a1);
                a2 = ffma2(p3, w2[2][3], a2); a3 = ffma2(p3, w2[3][3], a3);
                a0 = ffma2(p4, w2[0][4], a0); a1 = ffma2(p4, w2[1][4], a1);
                a2 = ffma2(p4, w2[2][4], a2); a3 = ffma2(p4, w2[3][4], a3);
                a0 = ffma2(p5, w2[0][5], a0); a1 = ffma2(p5, w2[1][5], a1);
                a2 = ffma2(p5, w2[2][5], a2); a3 = ffma2(p5, w2[3][5], a3);
                a0 = ffma2(p6, w2[0][6], a0); a1 = ffma2(p6, w2[1][6], a1);
                a2 = ffma2(p6, w2[2][6], a2); a3 = ffma2(p6, w2[3][6], a3);
                a0 = ffma2(p7, w2[0][7], a0); a1 = ffma2(p7, w2[1][7], a1);
                a2 = ffma2(p7, w2[2][7], a2); a3 = ffma2(p7, w2[3][7], a3);
                a0 = ffma2(p8, w2[0][8], a0); a1 = ffma2(p8, w2[1][8], a1);
                a2 = ffma2(p8, w2[2][8], a2); a3 = ffma2(p8, w2[3][8], a3);
                a0 = ffma2(p9, w2[0][9], a0); a1 = ffma2(p9, w2[1][9], a1);
                a2 = ffma2(p9, w2[2][9], a2); a3 = ffma2(p9, w2[3][9], a3);
                v0 = pair_sum_bias(a0, bp[0]);
                v1 = pair_sum_bias(a1, bp[1]);
                v2 = pair_sum_bias(a2, bp[2]);
                v3 = pair_sum_bias(a3, bp[3]);
            } else {
                const float t = __uint_as_float((unsigned)(meta >> 32));
                v0 = fast_cos(fmaf(t, wfb[0], bfb[0]));
                v1 = fast_cos(fmaf(t, wfb[1], bfb[1]));
                v2 = fast_cos(fmaf(t, wfb[2], bfb[2]));
                v3 = fast_cos(fmaf(t, wfb[3], bfb[3]));
            }
            if (r < B)  // streaming store: output is write-once, keep table in L2
                __stcs(((float4*)(out + (size_t)r * OUT_DIM)) + lane,
                       make_float4(v0, v1, v2, v3));
        }
        c = cn;
        buf ^= 1;
    }
}

extern "C" void kernel_launch(void* const* d_in, const int* in_sizes, int n_in,
                              void* d_out, int out_size)
{
    // metadata order: 0 src, 1 dst, 2 t_diff, 3 kde_idx, 4 kde_mask,
    //                 5 kde_table, 6 W_proj, 7 b_proj, 8 W_fb, 9 b_fb
    const float* t_diff    = (const float*)d_in[2];
    const void*  kde_idx   = d_in[3];
    const void*  kde_mask  = d_in[4];
    const float* kde_table = (const float*)d_in[5];
    const float* W_proj    = (const float*)d_in[6];
    const float* b_proj    = (const float*)d_in[7];
    const float* W_fb      = (const float*)d_in[8];
    const float* b_fb      = (const float*)d_in[9];
    float* out = (float*)d_out;
    const int B = in_sizes[2];

    const int grid = 148 * BLOCKS_PER_SM;
    kde_time_encoder_kernel<<<grid, OUT_DIM>>>(
        t_diff, kde_idx, kde_mask, kde_table,
        W_proj, b_proj, W_fb, b_fb, out, B);
}